// round 15
// baseline (speedup 1.0000x reference)
#include <cuda_runtime.h>

// ---------------- problem constants ----------------
#define NN    16384     // nodes (B*NPER)
#define EE    65536     // edges
#define HH    32        // hidden
#define BBAT  32        // batch
#define NPERB 512
#define NLAY  4
#define KTOT  320       // 256 (c (x) x) + 32 (bias path) + 32 (root path)
#define NPB   32        // nodes per layer-block
#define APITCH 324      // A pitch: rows 16B-aligned; rg-rows on banks 0/4/8/12 -> conflict-free
#define OFF_CS 10368    // 32*324
#define SMEMF  10496
#define SMEMB  (SMEMF * 4)   // 41984 B -> 3 blocks/SM

// ---------------- scratch (static device globals; zero at load) ----------------
__device__ __align__(128) float g_xbuf[2][NN * HH];    // ping-pong node features
__device__ __align__(128) float g_B[NLAY * KTOT * HH]; // chunk-major: [l][kc][col][j], j=k%4
__device__ int      g_deg[NN];                         // zeroed by k_final for next replay
__device__ float    g_invdeg[NN];
__device__ int      g_rowstart[NN + 1];
__device__ int      g_cursor[NN];
__device__ unsigned g_payload[EE];                     // (src<<18)|(dst<<4)|attr, grouped by dst
__device__ int      g_bsum[64];

// ---------------- f32x2 helpers ----------------
__device__ __forceinline__ unsigned long long fma2(unsigned long long a,
                                                   unsigned long long b,
                                                   unsigned long long c) {
    unsigned long long d;
    asm("fma.rn.f32x2 %0, %1, %2, %3;" : "=l"(d) : "l"(a), "l"(b), "l"(c));
    return d;
}
__device__ __forceinline__ float fold2(unsigned long long v) {
    unsigned int lo, hi;
    asm("mov.b64 {%0, %1}, %2;" : "=r"(lo), "=r"(hi) : "l"(v));
    return __uint_as_float(lo) + __uint_as_float(hi);
}

// ================= K1: fused setup (init x, build B chunk-major, count degs) ==
__global__ __launch_bounds__(256) void k_setup(const int* __restrict__ xn,
                                               const float* __restrict__ nemb,
                                               const float* __restrict__ lin_w,
                                               const float* __restrict__ lin_b,
                                               const float* __restrict__ root_w,
                                               const int* __restrict__ edge_index) {
    int b = blockIdx.x, t = threadIdx.x;
    if (b < 512) {
        int i = b * 256 + t;                 // < NN*HH/4
        int node = i >> 3, q = i & 7;
        float4 v = __ldg((const float4*)(nemb + xn[node] * HH + q * 4));
        ((float4*)g_xbuf[0])[i] = v;
    } else if (b < 672) {
        int i = (b - 512) * 256 + t;         // < 40960
        int l = i / 10240;
        int rem = i - l * 10240;
        int kc = rem >> 7;                   // k-chunk 0..79
        int r2 = rem & 127;
        int c = r2 >> 2, j = r2 & 3;
        int k = kc * 4 + j;
        float v;
        if (k < 256)      v = lin_w[l * 8192 + (k >> 5) * 1024 + (k & 31) * 32 + c];
        else if (k < 288) v = lin_b[l * 1024 + (k - 256) * 32 + c];
        else              v = root_w[l * 1024 + (k - 288) * 32 + c];
        g_B[i] = v;
    } else {
        int i = (b - 672) * 256 + t;         // < EE/4
        int4 d4 = __ldg((const int4*)(edge_index + EE) + i);
        atomicAdd(&g_deg[d4.x], 1);
        atomicAdd(&g_deg[d4.y], 1);
        atomicAdd(&g_deg[d4.z], 1);
        atomicAdd(&g_deg[d4.w], 1);
    }
}

// ================= K2/K3: hierarchical scan ==================================
__global__ __launch_bounds__(256) void k_scan1() {
    __shared__ int sw[8];
    int tid = threadIdx.x, w = tid >> 5, lane = tid & 31;
    int n = blockIdx.x * 256 + tid;
    int d = g_deg[n];
    int s = d;
#pragma unroll
    for (int off = 16; off; off >>= 1) s += __shfl_down_sync(0xFFFFFFFFu, s, off);
    if (lane == 0) sw[w] = s;
    __syncthreads();
    if (tid == 0) {
        int tot = 0;
#pragma unroll
        for (int j = 0; j < 8; j++) tot += sw[j];
        g_bsum[blockIdx.x] = tot;
    }
}

__global__ __launch_bounds__(256) void k_scan2() {
    __shared__ int sb[64];
    __shared__ int sw[8];
    int tid = threadIdx.x, w = tid >> 5, lane = tid & 31;
    int n = blockIdx.x * 256 + tid;
    if (tid < 64) sb[tid] = g_bsum[tid];
    int d = g_deg[n];
    __syncthreads();
    int base = 0;
    for (int j = 0; j < blockIdx.x; j++) base += sb[j];
    int incl = d;
#pragma unroll
    for (int off = 1; off < 32; off <<= 1) {
        int v = __shfl_up_sync(0xFFFFFFFFu, incl, off);
        if (lane >= off) incl += v;
    }
    if (lane == 31) sw[w] = incl;
    __syncthreads();
    int woff = 0;
#pragma unroll
    for (int j = 0; j < 8; j++) if (j < w) woff += sw[j];
    int excl = base + woff + incl - d;
    g_rowstart[n] = excl;
    g_cursor[n]   = excl;
    g_invdeg[n]   = 1.0f / (float)(d > 0 ? d : 1);
    if (n == NN - 1) g_rowstart[NN] = excl + d;
}

// ================= K4: scatter edges into CSR (packed with dst) ===============
__global__ __launch_bounds__(256) void k_scatter(const int* __restrict__ edge_index,
                                                 const int* __restrict__ edge_attr) {
    int e = blockIdx.x * 256 + threadIdx.x;
    int dd = edge_index[EE + e];
    int pos = atomicAdd(&g_cursor[dd], 1);
    g_payload[pos] = ((unsigned)edge_index[e] << 18) | ((unsigned)dd << 4)
                   | (unsigned)edge_attr[e];
}

// ================= fused layer ================================================
// Phase 1 (edge agg, EDGE-PARALLEL): the block's 32 nodes own the contiguous
//   CSR range [rowstart[n0], rowstart[n0+32]) (~128 edges). Split EVENLY over
//   8 warps (~16 each, zero straggler variance). Each warp register-accumulates
//   acc[9] (lane = feature) and flushes to As via smem atomicAdd on dst-change
//   (~6 flushes; consecutive-lane addresses -> conflict-free).
// Phase 1b: scale cols 0..287 by 1/deg; write root cols 288..319 = own x.
// Phase 2 (GEMM): warp = (ks: k-slice of 80) x (rh: row-half of 16).
//   Per 4-k: 4 LDS.128 A (conflict-free) + 4 LDG.128 B (chunk-major, L1-hot)
//   + 32 FFMA2, unroll 2. Phase 3: 4 k-partials reduced via smem.
__global__ __launch_bounds__(256, 3) void k_layer(const float* __restrict__ eemb,
                                                  const float* __restrict__ conv_b,
                                                  int inbuf, int l, int do_relu) {
    extern __shared__ float smem[];
    float* As = smem;
    float* cs = smem + OFF_CS;
    int tid = threadIdx.x;
    int n0 = blockIdx.x * NPB;
    const float* __restrict__ xin = g_xbuf[inbuf];

    // zero A accumulation region (cols 0..287; zero whole rows for simplicity)
#pragma unroll
    for (int i = 0; i < 11; i++) {
        int idx = tid + i * 256;
        if (idx < 2592) ((float4*)As)[idx] = make_float4(0.f, 0.f, 0.f, 0.f);
    }
    if (tid < 128) cs[tid] = fmaxf(eemb[l * 128 + tid], 0.0f);

    int w = tid >> 5, lane = tid & 31;

    // block edge range, split evenly over warps
    int e0 = g_rowstart[n0];
    int e1 = g_rowstart[n0 + NPB];
    int cnt = e1 - e0;
    int per = (cnt + 7) >> 3;
    int s  = e0 + w * per;
    int en = min(s + per, e1);

    __syncthreads();   // As zeroed + cs ready

    float a[9];
#pragma unroll
    for (int j = 0; j < 9; j++) a[j] = 0.0f;
    int cur = -1;

    unsigned p0 = (s < en) ? g_payload[s] : 0u;
    float   xv0 = (s < en) ? __ldg(&xin[(p0 >> 18) * HH + lane]) : 0.0f;

    for (int t = s; t < en; t++) {
        unsigned p1 = (t + 1 < en) ? g_payload[t + 1] : 0u;
        float   xv1 = (t + 1 < en) ? __ldg(&xin[(p1 >> 18) * HH + lane]) : 0.0f;

        int dst = (int)((p0 >> 4) & 0x3FFFu);
        if (dst != cur) {
            if (cur >= 0) {
                float* Ar = As + (cur - n0) * APITCH + lane;
#pragma unroll
                for (int j = 0; j < 9; j++) { atomicAdd(&Ar[j * 32], a[j]); a[j] = 0.0f; }
            }
            cur = dst;
        }
        const float* cc = &cs[(p0 & 15u) * 8];
#pragma unroll
        for (int j = 0; j < 8; j++) a[j] = fmaf(cc[j], xv0, a[j]);
        a[8] += xv0;

        p0 = p1; xv0 = xv1;
    }
    if (cur >= 0) {
        float* Ar = As + (cur - n0) * APITCH + lane;
#pragma unroll
        for (int j = 0; j < 9; j++) atomicAdd(&Ar[j * 32], a[j]);
    }
    __syncthreads();   // all flushes visible

    // Phase 1b: scale + root write. thread (r = tid>>3, q = tid&7)
    {
        int r = tid >> 3, q = tid & 7;
        float inv = g_invdeg[n0 + r];
        float* Arow = As + r * APITCH;
#pragma unroll
        for (int i = 0; i < 9; i++) {
            float4* p = (float4*)(Arow + q * 36 + i * 4);
            float4 v = *p;
            v.x *= inv; v.y *= inv; v.z *= inv; v.w *= inv;
            *p = v;
        }
        float4 xr = __ldg((const float4*)(xin + (n0 + r) * HH) + q);
        *(float4*)(Arow + 288 + q * 4) = xr;
    }
    __syncthreads();

    // ---------------- GEMM phase ----------------
    int ks = w & 3, rh = w >> 2;
    int rg = lane >> 3, cg = lane & 7;
    const float4* __restrict__ B4 = (const float4*)(g_B + l * 10240);

    unsigned long long ac[16];
#pragma unroll
    for (int i = 0; i < 16; i++) ac[i] = 0ull;

    int kc0 = ks * 20;
#pragma unroll 2
    for (int g = 0; g < 20; g++) {
        int kc = kc0 + g;
        ulonglong2 a2[4], b2[4];
#pragma unroll
        for (int rr = 0; rr < 4; rr++) {
            float4 av = *(const float4*)(As + (rh * 16 + rr * 4 + rg) * APITCH + kc * 4);
            a2[rr] = *reinterpret_cast<ulonglong2*>(&av);
        }
#pragma unroll
        for (int ci = 0; ci < 4; ci++) {
            float4 bx = __ldg(B4 + kc * 32 + cg + 8 * ci);
            b2[ci] = *reinterpret_cast<ulonglong2*>(&bx);
        }
#pragma unroll
        for (int rr = 0; rr < 4; rr++)
#pragma unroll
            for (int ci = 0; ci < 4; ci++) {
                ac[rr * 4 + ci] = fma2(a2[rr].x, b2[ci].x, ac[rr * 4 + ci]);
                ac[rr * 4 + ci] = fma2(a2[rr].y, b2[ci].y, ac[rr * 4 + ci]);
            }
    }
    __syncthreads();   // all warps done reading As; reuse smem for partials

    // stage partials: S[ks][row][33]
    float* S = smem;
#pragma unroll
    for (int rr = 0; rr < 4; rr++)
#pragma unroll
        for (int ci = 0; ci < 4; ci++)
            S[ks * 1056 + (rh * 16 + rr * 4 + rg) * 33 + cg + 8 * ci] = fold2(ac[rr * 4 + ci]);
    __syncthreads();

    // reduce 4 partials + epilogue
    {
        int row = tid >> 3, c4 = (tid & 7) * 4;
        float4 sv;
        sv.x = conv_b[l * HH + c4 + 0];
        sv.y = conv_b[l * HH + c4 + 1];
        sv.z = conv_b[l * HH + c4 + 2];
        sv.w = conv_b[l * HH + c4 + 3];
#pragma unroll
        for (int p = 0; p < 4; p++) {
            const float* Sp = S + p * 1056 + row * 33 + c4;
            sv.x += Sp[0]; sv.y += Sp[1]; sv.z += Sp[2]; sv.w += Sp[3];
        }
        if (do_relu) {
            sv.x = fmaxf(sv.x, 0.f); sv.y = fmaxf(sv.y, 0.f);
            sv.z = fmaxf(sv.z, 0.f); sv.w = fmaxf(sv.w, 0.f);
        }
        float* __restrict__ xout = g_xbuf[inbuf ^ 1];
        *(float4*)&xout[(n0 + row) * HH + c4] = sv;
    }
}

// ================= readout (+ zero g_deg for next replay) ====================
__global__ __launch_bounds__(256) void k_final(const int* __restrict__ metal_idx,
                                               const int* __restrict__ loop_edge,
                                               const int* __restrict__ loop_pair,
                                               const float* __restrict__ f_w,
                                               const float* __restrict__ f_b,
                                               float* __restrict__ out) {
    int gid = blockIdx.x * 256 + threadIdx.x;
    if (gid < NN) g_deg[gid] = 0;

    int gw = blockIdx.x * 8 + (threadIdx.x >> 5);
    int lane = threadIdx.x & 31;
    int b = gw >> 7, p = gw & 127;
    const float* __restrict__ x = g_xbuf[0];   // NLAY even -> final in buf 0

    int mnode = b * NPERB + metal_idx[b];
    float xm = x[mnode * HH + lane];

    int s, t;
    if (p < 64) {
        s = loop_edge[(b * 64 + p) * 2 + 0];
        t = loop_edge[(b * 64 + p) * 2 + 1];
    } else {
        int q = p - 64;
        s = loop_pair[(b * 64 + q) * 2 + 0];
        t = loop_pair[(b * 64 + q) * 2 + 1];
    }
    float xs = x[(b * NPERB + s) * HH + lane];
    float xt = x[(b * NPERB + t) * HH + lane];
    float v  = xm * (xs + xt) - xs * xt;
    float fh = xm * f_w[lane];
#pragma unroll
    for (int off = 16; off; off >>= 1) {
        v  += __shfl_xor_sync(0xFFFFFFFFu, v, off);
        fh += __shfl_xor_sync(0xFFFFFFFFu, fh, off);
    }
    if (lane == 0)
        out[b * 128 + p] = (p < 64) ? (v - (fh + f_b[0])) : -v;
}

// ================= launch ====================================================
extern "C" void kernel_launch(void* const* d_in, const int* in_sizes, int n_in,
                              void* d_out, int out_size) {
    const int*   x_nodes    = (const int*)d_in[0];
    const int*   edge_index = (const int*)d_in[1];
    const int*   edge_attr  = (const int*)d_in[2];
    const int*   metal_idx  = (const int*)d_in[3];
    const int*   loop_edge  = (const int*)d_in[4];
    const int*   loop_pair  = (const int*)d_in[5];
    const float* node_emb   = (const float*)d_in[6];
    const float* edge_emb   = (const float*)d_in[7];
    const float* lin_w      = (const float*)d_in[8];
    const float* lin_b      = (const float*)d_in[9];
    const float* root_w     = (const float*)d_in[10];
    const float* conv_b     = (const float*)d_in[11];
    const float* f_w        = (const float*)d_in[12];
    const float* f_b        = (const float*)d_in[13];
    float* out = (float*)d_out;

    cudaFuncSetAttribute(k_layer, cudaFuncAttributeMaxDynamicSharedMemorySize, SMEMB);

    k_setup  <<<736, 256>>>(x_nodes, node_emb, lin_w, lin_b, root_w, edge_index);
    k_scan1  <<<64, 256>>>();
    k_scan2  <<<64, 256>>>();
    k_scatter<<<256, 256>>>(edge_index, edge_attr);

    for (int l = 0; l < NLAY; l++) {
        int inb = l & 1;
        k_layer<<<NN / NPB, 256, SMEMB>>>(edge_emb, conv_b, inb, l, (l < NLAY - 1) ? 1 : 0);
    }

    k_final<<<512, 256>>>(metal_idx, loop_edge, loop_pair, f_w, f_b, out);
}

// round 17
// speedup vs baseline: 1.1225x; 1.1225x over previous
#include <cuda_runtime.h>

// ---------------- problem constants ----------------
#define NN    16384     // nodes (B*NPER)
#define EE    65536     // edges
#define HH    32        // hidden
#define BBAT  32        // batch
#define NPERB 512
#define NLAY  4
#define KTOT  320
#define NPB   16        // nodes per layer-block
#define APITCH 324      // A pitch: rows 16B-aligned; rg-rows on banks 0/4/8/12 -> conflict-free
#define OFF_CS 5184     // 16*324
#define SMEMF  5312
#define SMEMB  (SMEMF * 4)   // 21248 B -> 4 blocks/SM (85KB), regs <= 64

// ---------------- scratch (static device globals; zero at load) ----------------
__device__ __align__(128) float g_xbuf[2][NN * HH];    // ping-pong node features
__device__ __align__(128) float g_B[NLAY * KTOT * HH]; // chunk-major: [l][kc][col][j], j=k%4
__device__ int   g_deg[NN];                            // zeroed by k_final for next replay
__device__ float g_invdeg[NN];
__device__ int   g_rowstart[NN + 1];
__device__ int   g_cursor[NN];
__device__ int   g_payload[EE];                        // (src<<4)|attr, grouped by dst
__device__ int   g_bsum[64];
__device__ int   g_barrier;                            // grid barrier (reset each run)
__device__ int   g_done;

// ---------------- f32x2 helpers ----------------
__device__ __forceinline__ unsigned long long fma2(unsigned long long a,
                                                   unsigned long long b,
                                                   unsigned long long c) {
    unsigned long long d;
    asm("fma.rn.f32x2 %0, %1, %2, %3;" : "=l"(d) : "l"(a), "l"(b), "l"(c));
    return d;
}
__device__ __forceinline__ float fold2(unsigned long long v) {
    unsigned int lo, hi;
    asm("mov.b64 {%0, %1}, %2;" : "=r"(lo), "=r"(hi) : "l"(v));
    return __uint_as_float(lo) + __uint_as_float(hi);
}

// ================= K1: fused setup (init x, build B chunk-major, count degs) ==
__global__ __launch_bounds__(256) void k_setup(const int* __restrict__ xn,
                                               const float* __restrict__ nemb,
                                               const float* __restrict__ lin_w,
                                               const float* __restrict__ lin_b,
                                               const float* __restrict__ root_w,
                                               const int* __restrict__ edge_index) {
    int b = blockIdx.x, t = threadIdx.x;
    if (b < 512) {
        int i = b * 256 + t;                 // < NN*HH/4
        int node = i >> 3, q = i & 7;
        float4 v = __ldg((const float4*)(nemb + xn[node] * HH + q * 4));
        ((float4*)g_xbuf[0])[i] = v;
    } else if (b < 672) {
        int i = (b - 512) * 256 + t;         // < 40960
        int l = i / 10240;
        int rem = i - l * 10240;
        int kc = rem >> 7;
        int r2 = rem & 127;
        int c = r2 >> 2, j = r2 & 3;
        int k = kc * 4 + j;
        float v;
        if (k < 256)      v = lin_w[l * 8192 + (k >> 5) * 1024 + (k & 31) * 32 + c];
        else if (k < 288) v = lin_b[l * 1024 + (k - 256) * 32 + c];
        else              v = root_w[l * 1024 + (k - 288) * 32 + c];
        g_B[i] = v;
    } else {
        int i = (b - 672) * 256 + t;         // < EE/4
        int4 d4 = __ldg((const int4*)(edge_index + EE) + i);
        atomicAdd(&g_deg[d4.x], 1);
        atomicAdd(&g_deg[d4.y], 1);
        atomicAdd(&g_deg[d4.z], 1);
        atomicAdd(&g_deg[d4.w], 1);
    }
}

// ================= K2: fused scan + scatter (64 blocks resident) ==============
__global__ __launch_bounds__(256) void k_scan_scatter(const int* __restrict__ edge_index,
                                                      const int* __restrict__ edge_attr) {
    __shared__ int sw[8];
    __shared__ int sb[64];
    int tid = threadIdx.x, w = tid >> 5, lane = tid & 31, b = blockIdx.x;
    int n = b * 256 + tid;
    int d = g_deg[n];

    int incl = d;
#pragma unroll
    for (int off = 1; off < 32; off <<= 1) {
        int v = __shfl_up_sync(0xFFFFFFFFu, incl, off);
        if (lane >= off) incl += v;
    }
    if (lane == 31) sw[w] = incl;
    __syncthreads();
    int woff = 0, btot = 0;
#pragma unroll
    for (int j = 0; j < 8; j++) { if (j < w) woff += sw[j]; btot += sw[j]; }

    if (tid == 0) {
        g_bsum[b] = btot;
        __threadfence();
        atomicAdd(&g_barrier, 1);
        while (atomicAdd(&g_barrier, 0) < 64) { }
        __threadfence();
    }
    __syncthreads();

    if (tid < 64) sb[tid] = g_bsum[tid];
    __syncthreads();
    int base = 0;
    for (int j = 0; j < b; j++) base += sb[j];

    int excl = base + woff + incl - d;
    g_rowstart[n] = excl;
    g_cursor[n]   = excl;
    g_invdeg[n]   = 1.0f / (float)(d > 0 ? d : 1);
    if (n == NN - 1) g_rowstart[NN] = excl + d;

    __threadfence();
    __syncthreads();
    if (tid == 0) {
        atomicAdd(&g_barrier, 1);
        while (atomicAdd(&g_barrier, 0) < 128) { }
        __threadfence();
    }
    __syncthreads();

#pragma unroll
    for (int q = 0; q < 4; q++) {
        int e = b * 1024 + q * 256 + tid;
        int dd = edge_index[EE + e];
        int pos = atomicAdd(&g_cursor[dd], 1);
        g_payload[pos] = (edge_index[e] << 4) | edge_attr[e];
    }
    __syncthreads();
    if (tid == 0) {
        int c = atomicAdd(&g_done, 1);
        if (c == 63) { g_done = 0; g_barrier = 0; __threadfence(); }
    }
}

// ================= fused layer (16 nodes / 256 threads / 4 blocks per SM) =====
// Phase 1 (edge agg, R8 warp-pair): warp PAIR per 4 nodes; sub-warp s takes
//   edges s, s+2, ... -> serial depth = max(ceil(deg/2)) ~ 6 vs 12.
//   Merge: sub0 writes As scaled, sync, sub1 adds scaled.
// Phase 2 (GEMM, 2x4 tile): warp = (ks: k-slice of 80) x (rh: row-half of 8).
//   lane: rg=lane>>3, cg=lane&7; rows {rh*8+rr*4+rg}, rr in 0..1.
//   Per 4-k: 2 LDS.128 A (conflict-free) + 4 LDG.128 B (chunk-major, L1-hot)
//   + 16 FFMA2, unroll 2. acc = 16 regs -> ~50 live -> 4 blocks/SM.
// Phase 3: 4 k-partials staged (smem reuse), reduce + epilogue.
__global__ __launch_bounds__(256, 4) void k_layer(const float* __restrict__ eemb,
                                                  const float* __restrict__ conv_b,
                                                  int inbuf, int l, int do_relu) {
    extern __shared__ float smem[];
    float* As = smem;
    float* cs = smem + OFF_CS;
    int tid = threadIdx.x;
    if (tid < 128) cs[tid] = fmaxf(eemb[l * 128 + tid], 0.0f);

    const float* __restrict__ xin = g_xbuf[inbuf];
    int w = tid >> 5, lane = tid & 31;
    int quad = w >> 1, sub = w & 1;
    int nl0 = quad * 4;
    int ng0 = blockIdx.x * NPB + nl0;

    int rs = 0;
    if (lane < 5) rs = g_rowstart[ng0 + lane];
    int r0 = __shfl_sync(0xFFFFFFFFu, rs, 0);
    int r1 = __shfl_sync(0xFFFFFFFFu, rs, 1);
    int r2 = __shfl_sync(0xFFFFFFFFu, rs, 2);
    int r3 = __shfl_sync(0xFFFFFFFFu, rs, 3);
    int r4 = __shfl_sync(0xFFFFFFFFu, rs, 4);
    int beg[4] = {r0 + sub, r1 + sub, r2 + sub, r3 + sub};
    int cnt[4];
    cnt[0] = (r1 - r0 - sub + 1) >> 1;
    cnt[1] = (r2 - r1 - sub + 1) >> 1;
    cnt[2] = (r3 - r2 - sub + 1) >> 1;
    cnt[3] = (r4 - r3 - sub + 1) >> 1;
    int maxc = max(max(cnt[0], cnt[1]), max(cnt[2], cnt[3]));

    float acc[4][9];
#pragma unroll
    for (int i = 0; i < 4; i++)
#pragma unroll
        for (int j = 0; j < 9; j++) acc[i][j] = 0.0f;

    __syncthreads();   // cs ready

    int pcur[4];
#pragma unroll
    for (int i = 0; i < 4; i++) pcur[i] = (0 < cnt[i]) ? g_payload[beg[i]] : -1;

    for (int t = 0; t < maxc; t++) {
        int pnext[4];
#pragma unroll
        for (int i = 0; i < 4; i++)
            pnext[i] = (t + 1 < cnt[i]) ? g_payload[beg[i] + 2 * (t + 1)] : -1;
        float xv[4];
#pragma unroll
        for (int i = 0; i < 4; i++)
            xv[i] = (pcur[i] >= 0) ? __ldg(&xin[(pcur[i] >> 4) * HH + lane]) : 0.0f;
#pragma unroll
        for (int i = 0; i < 4; i++) {
            const float* cc = &cs[(pcur[i] & 15) * 8];
#pragma unroll
            for (int j = 0; j < 8; j++) acc[i][j] = fmaf(cc[j], xv[i], acc[i][j]);
            acc[i][8] += xv[i];
        }
#pragma unroll
        for (int i = 0; i < 4; i++) pcur[i] = pnext[i];
    }

    // merge half-sums: sub0 writes (scaled) + root cols; sync; sub1 adds
    if (sub == 0) {
#pragma unroll
        for (int i = 0; i < 4; i++) {
            float inv = g_invdeg[ng0 + i];
            float* Arow = As + (nl0 + i) * APITCH;
#pragma unroll
            for (int j = 0; j < 9; j++) Arow[j * 32 + lane] = acc[i][j] * inv;
            Arow[288 + lane] = xin[(ng0 + i) * HH + lane];
        }
    }
    __syncthreads();
    if (sub == 1) {
#pragma unroll
        for (int i = 0; i < 4; i++) {
            float inv = g_invdeg[ng0 + i];
            float* Arow = As + (nl0 + i) * APITCH;
#pragma unroll
            for (int j = 0; j < 9; j++) Arow[j * 32 + lane] += acc[i][j] * inv;
        }
    }
    __syncthreads();

    // ---------------- GEMM phase: 2x4 thread tile ----------------
    int ks = w & 3, rh = w >> 2;        // k-slice (20 chunks); row-half of 8
    int rg = lane >> 3, cg = lane & 7;
    const float4* __restrict__ B4 = (const float4*)(g_B + l * 10240);

    unsigned long long ac[8];           // [rr(2)][ci(4)]
#pragma unroll
    for (int i = 0; i < 8; i++) ac[i] = 0ull;

    int kc0 = ks * 20;
#pragma unroll 2
    for (int g = 0; g < 20; g++) {
        int kc = kc0 + g;
        ulonglong2 a2[2], b2[4];
#pragma unroll
        for (int rr = 0; rr < 2; rr++) {
            float4 av = *(const float4*)(As + (rh * 8 + rr * 4 + rg) * APITCH + kc * 4);
            a2[rr] = *reinterpret_cast<ulonglong2*>(&av);
        }
#pragma unroll
        for (int ci = 0; ci < 4; ci++) {
            float4 bx = __ldg(B4 + kc * 32 + cg + 8 * ci);
            b2[ci] = *reinterpret_cast<ulonglong2*>(&bx);
        }
#pragma unroll
        for (int rr = 0; rr < 2; rr++)
#pragma unroll
            for (int ci = 0; ci < 4; ci++) {
                ac[rr * 4 + ci] = fma2(a2[rr].x, b2[ci].x, ac[rr * 4 + ci]);
                ac[rr * 4 + ci] = fma2(a2[rr].y, b2[ci].y, ac[rr * 4 + ci]);
            }
    }
    __syncthreads();   // all warps done reading As; reuse smem for partials

    // stage partials: S[ks][row(16)][33]
    float* S = smem;
#pragma unroll
    for (int rr = 0; rr < 2; rr++)
#pragma unroll
        for (int ci = 0; ci < 4; ci++)
            S[ks * 528 + (rh * 8 + rr * 4 + rg) * 33 + cg + 8 * ci] = fold2(ac[rr * 4 + ci]);
    __syncthreads();

    // reduce 4 partials + epilogue (16 rows x 16 col-pairs = 256 threads)
    {
        int row = tid >> 4, c2 = (tid & 15) * 2;
        float2 sv;
        sv.x = conv_b[l * HH + c2 + 0];
        sv.y = conv_b[l * HH + c2 + 1];
#pragma unroll
        for (int p = 0; p < 4; p++) {
            const float* Sp = S + p * 528 + row * 33 + c2;
            sv.x += Sp[0]; sv.y += Sp[1];
        }
        if (do_relu) { sv.x = fmaxf(sv.x, 0.f); sv.y = fmaxf(sv.y, 0.f); }
        float* __restrict__ xout = g_xbuf[inbuf ^ 1];
        *(float2*)&xout[(blockIdx.x * NPB + row) * HH + c2] = sv;
    }
}

// ================= readout (+ zero g_deg for next replay) ====================
__global__ __launch_bounds__(256) void k_final(const int* __restrict__ metal_idx,
                                               const int* __restrict__ loop_edge,
                                               const int* __restrict__ loop_pair,
                                               const float* __restrict__ f_w,
                                               const float* __restrict__ f_b,
                                               float* __restrict__ out) {
    int gid = blockIdx.x * 256 + threadIdx.x;
    if (gid < NN) g_deg[gid] = 0;

    int gw = blockIdx.x * 8 + (threadIdx.x >> 5);
    int lane = threadIdx.x & 31;
    int b = gw >> 7, p = gw & 127;
    const float* __restrict__ x = g_xbuf[0];   // NLAY even -> final in buf 0

    int mnode = b * NPERB + metal_idx[b];
    float xm = x[mnode * HH + lane];

    int s, t;
    if (p < 64) {
        s = loop_edge[(b * 64 + p) * 2 + 0];
        t = loop_edge[(b * 64 + p) * 2 + 1];
    } else {
        int q = p - 64;
        s = loop_pair[(b * 64 + q) * 2 + 0];
        t = loop_pair[(b * 64 + q) * 2 + 1];
    }
    float xs = x[(b * NPERB + s) * HH + lane];
    float xt = x[(b * NPERB + t) * HH + lane];
    float v  = xm * (xs + xt) - xs * xt;
    float fh = xm * f_w[lane];
#pragma unroll
    for (int off = 16; off; off >>= 1) {
        v  += __shfl_xor_sync(0xFFFFFFFFu, v, off);
        fh += __shfl_xor_sync(0xFFFFFFFFu, fh, off);
    }
    if (lane == 0)
        out[b * 128 + p] = (p < 64) ? (v - (fh + f_b[0])) : -v;
}

// ================= launch ====================================================
extern "C" void kernel_launch(void* const* d_in, const int* in_sizes, int n_in,
                              void* d_out, int out_size) {
    const int*   x_nodes    = (const int*)d_in[0];
    const int*   edge_index = (const int*)d_in[1];
    const int*   edge_attr  = (const int*)d_in[2];
    const int*   metal_idx  = (const int*)d_in[3];
    const int*   loop_edge  = (const int*)d_in[4];
    const int*   loop_pair  = (const int*)d_in[5];
    const float* node_emb   = (const float*)d_in[6];
    const float* edge_emb   = (const float*)d_in[7];
    const float* lin_w      = (const float*)d_in[8];
    const float* lin_b      = (const float*)d_in[9];
    const float* root_w     = (const float*)d_in[10];
    const float* conv_b     = (const float*)d_in[11];
    const float* f_w        = (const float*)d_in[12];
    const float* f_b        = (const float*)d_in[13];
    float* out = (float*)d_out;

    cudaFuncSetAttribute(k_layer, cudaFuncAttributeMaxDynamicSharedMemorySize, SMEMB);

    k_setup       <<<736, 256>>>(x_nodes, node_emb, lin_w, lin_b, root_w, edge_index);
    k_scan_scatter<<<64, 256>>>(edge_index, edge_attr);

    for (int l = 0; l < NLAY; l++) {
        int inb = l & 1;
        k_layer<<<NN / NPB, 256, SMEMB>>>(edge_emb, conv_b, inb, l, (l < NLAY - 1) ? 1 : 0);
    }

    k_final<<<512, 256>>>(metal_idx, loop_edge, loop_pair, f_w, f_b, out);
}